// round 1
// baseline (speedup 1.0000x reference)
#include <cuda_runtime.h>
#include <cstdint>
#include <math.h>

// Problem constants
#define BB 64
#define TT 2048
#define II 64
#define HH 128

// ---------- packed f32x2 helpers ----------
__device__ __forceinline__ unsigned long long ffma2(unsigned long long a,
                                                    unsigned long long b,
                                                    unsigned long long c) {
    unsigned long long d;
    asm("fma.rn.f32x2 %0, %1, %2, %3;" : "=l"(d) : "l"(a), "l"(b), "l"(c));
    return d;
}
__device__ __forceinline__ float2 unpack2(unsigned long long v) {
    float2 f;
    asm("mov.b64 {%0, %1}, %2;" : "=f"(f.x), "=f"(f.y) : "l"(v));
    return f;
}

// ============================================================================
// Phase 1: xw[b,t,i] = dot(x[b,t,:], W[i,:]) + b_ih[i] + b_hh[i]
// Written directly into the output region of d_out (overwritten in-place by
// the scan kernel later). One block = 64 (b,t) rows, 128 threads (one per i).
// Thread i holds W row i in 32 packed f32x2 registers.
// ============================================================================
__global__ __launch_bounds__(128) void xw_gemm_kernel(
    const float* __restrict__ x,
    const float* __restrict__ W,
    const float* __restrict__ b_ih,
    const float* __restrict__ b_hh,
    float* __restrict__ out)
{
    const int ROWS = 64;
    const int i = threadIdx.x;
    const long long row0 = (long long)blockIdx.x * ROWS;

    // Load W row i (64 floats) into 32 packed regs
    unsigned long long w[32];
    const ulonglong2* Wrow = (const ulonglong2*)(W + i * II);
#pragma unroll
    for (int k = 0; k < 16; k++) {
        ulonglong2 t = Wrow[k];
        w[2 * k]     = t.x;
        w[2 * k + 1] = t.y;
    }
    const float bias = b_ih[i] + b_hh[i];

    __shared__ __align__(16) float xs[2][II];

    const float4* xg = (const float4*)(x + row0 * II);  // 16 float4 per row

    // Pipeline: xs[0] <- row 0, pre <- row 1
    float4 pre = make_float4(0.f, 0.f, 0.f, 0.f);
    if (i < 16) {
        ((float4*)xs[0])[i] = xg[i];
        pre = xg[16 + i];
    }
    __syncthreads();

    for (int r = 0; r < ROWS; r++) {
        // issue prefetch of row r+2 early (hide latency behind compute)
        float4 nxt = make_float4(0.f, 0.f, 0.f, 0.f);
        if (i < 16) {
            int rr = (r + 2 < ROWS) ? (r + 2) : r;
            nxt = xg[rr * 16 + i];
        }

        // dot(W[i,:], x_row) with packed FMAs
        const ulonglong2* hv = (const ulonglong2*)xs[r & 1];
        unsigned long long a0 = 0ull, a1 = 0ull, a2 = 0ull, a3 = 0ull;
#pragma unroll
        for (int k = 0; k < 16; k += 2) {
            ulonglong2 hA = hv[k];
            ulonglong2 hB = hv[k + 1];
            a0 = ffma2(w[2 * k],     hA.x, a0);
            a1 = ffma2(w[2 * k + 1], hA.y, a1);
            a2 = ffma2(w[2 * k + 2], hB.x, a2);
            a3 = ffma2(w[2 * k + 3], hB.y, a3);
        }
        float2 f0 = unpack2(a0), f1 = unpack2(a1), f2 = unpack2(a2), f3 = unpack2(a3);
        float dot = ((f0.x + f0.y) + (f1.x + f1.y)) + ((f2.x + f2.y) + (f3.x + f3.y));

        out[(row0 + r) * HH + i] = dot + bias;

        // publish row r+1 into the other buffer, then sync
        if (i < 16) ((float4*)xs[(r + 1) & 1])[i] = pre;
        __syncthreads();
        pre = nxt;
    }
}

// ============================================================================
// Phase 2: sequential scan.  One block per batch element (64 blocks, 128 thr).
// Thread i holds U row i in 64 packed f32x2 registers (128 regs).
// h state in double-buffered smem; one __syncthreads per step.
// xw is read in-place from d_out (written by phase 1), prefetch distance 2,
// and overwritten with h_t.
// ============================================================================
__global__ __launch_bounds__(128, 1) void rnn_scan_kernel(
    const float* __restrict__ h0,
    const float* __restrict__ U,
    float* __restrict__ out)
{
    const int b = blockIdx.x;
    const int i = threadIdx.x;

    __shared__ __align__(16) float h_s[2][HH];

    // Load U row i (128 floats) into 64 packed regs
    unsigned long long u[64];
    const ulonglong2* Urow = (const ulonglong2*)(U + i * HH);
#pragma unroll
    for (int k = 0; k < 32; k++) {
        ulonglong2 t = Urow[k];
        u[2 * k]     = t.x;
        u[2 * k + 1] = t.y;
    }

    h_s[0][i] = h0[b * HH + i];

    float* op = out + (size_t)b * TT * HH + i;  // column i of batch b, step stride HH

    // prefetch distance 2 on xw
    float xw0 = op[0];
    float xw1 = op[HH];
    __syncthreads();

    int buf = 0;
#pragma unroll 1
    for (int t = 0; t < TT; t++) {
        // issue prefetch of xw[t+2] (still holds phase-1 data; this block only
        // overwrites position t at step t, so t+2 is untouched)
        int tp = (t + 2 < TT) ? (t + 2) : t;
        float xw2 = op[tp * HH];

        // dot(U[i,:], h) via broadcast LDS.128 + packed FMAs
        const ulonglong2* hv = (const ulonglong2*)h_s[buf];
        unsigned long long a0 = 0ull, a1 = 0ull, a2 = 0ull, a3 = 0ull;
#pragma unroll
        for (int k = 0; k < 32; k += 2) {
            ulonglong2 hA = hv[k];
            ulonglong2 hB = hv[k + 1];
            a0 = ffma2(u[2 * k],     hA.x, a0);
            a1 = ffma2(u[2 * k + 1], hA.y, a1);
            a2 = ffma2(u[2 * k + 2], hB.x, a2);
            a3 = ffma2(u[2 * k + 3], hB.y, a3);
        }
        float2 f0 = unpack2(a0), f1 = unpack2(a1), f2 = unpack2(a2), f3 = unpack2(a3);
        float dot = ((f0.x + f0.y) + (f1.x + f1.y)) + ((f2.x + f2.y) + (f3.x + f3.y));

        float v = tanhf(xw0 + dot);

        op[t * HH] = v;          // overwrite xw[t] with output h_t
        h_s[buf ^ 1][i] = v;     // publish new state
        __syncthreads();

        xw0 = xw1;
        xw1 = xw2;
        buf ^= 1;
    }

    // h_last  (h_s[buf] holds the final state after the last flip+sync)
    out[(size_t)BB * TT * HH + b * HH + i] = h_s[buf][i];
}

// ============================================================================
// Launch
// ============================================================================
extern "C" void kernel_launch(void* const* d_in, const int* in_sizes, int n_in,
                              void* d_out, int out_size)
{
    (void)in_sizes; (void)n_in; (void)out_size;
    const float* x    = (const float*)d_in[0];
    const float* h0   = (const float*)d_in[1];
    const float* W    = (const float*)d_in[2];
    const float* U    = (const float*)d_in[3];
    const float* b_ih = (const float*)d_in[4];
    const float* b_hh = (const float*)d_in[5];
    float* out = (float*)d_out;

    // Phase 1: input projection into out[0 .. B*T*H)
    xw_gemm_kernel<<<(BB * TT) / 64, 128>>>(x, W, b_ih, b_hh, out);
    // Phase 2: in-place sequential scan + h_last
    rnn_scan_kernel<<<BB, 128>>>(h0, U, out);
}